// round 4
// baseline (speedup 1.0000x reference)
#include <cuda_runtime.h>
#include <cuda_bf16.h>
#include <math.h>

// Problem constants
#define BB 128
#define TT 256
#define DD 256
#define HH 256

#define NBLK 128        // k_seq grid: 16 row-groups x 8 col-ranks
#define NGRP 16
#define GSZ  8          // CTAs per row-group (barrier scope)

typedef unsigned long long ull;

// ---------------- packed f32x2 helpers (Blackwell FFMA2 via PTX) ----------------
__device__ __forceinline__ ull pack2(float lo, float hi) {
    ull r; asm("mov.b64 %0, {%1, %2};" : "=l"(r) : "f"(lo), "f"(hi)); return r;
}
__device__ __forceinline__ void unpack2(float& lo, float& hi, ull v) {
    asm("mov.b64 {%0, %1}, %2;" : "=f"(lo), "=f"(hi) : "l"(v));
}
__device__ __forceinline__ ull fma2(ull a, ull b, ull c) {
    ull d; asm("fma.rn.f32x2 %0, %1, %2, %3;" : "=l"(d) : "l"(a), "l"(b), "l"(c));
    return d;
}

// ---------------- device scratch ----------------
__device__ float g_pre1[TT * BB * HH];   // pre1[t][b][h] = x_t @ Wih1_t + b1_t (row-major)
__device__ float g_h1T[2][HH * BB];      // hidden, COLUMN-major: [col*BB + row], ping-pong
__device__ float g_h2T[2][HH * BB];
__device__ float g_h2rm[BB * HH];        // final h2 forward, row-major (for fc)
__device__ float g_h1bk[BB * HH];
__device__ float g_h2bk[BB * HH];
__device__ unsigned g_bar[NGRP * 32];    // per-group barrier counters, 128B apart

// ---------------- reset kernel (per-replay determinism) ----------------
__global__ void k_reset() {
    unsigned i = blockIdx.x * blockDim.x + threadIdx.x;
    if (i < NGRP * 32) g_bar[i] = 0u;
    for (unsigned j = i; j < BB * HH; j += gridDim.x * blockDim.x) {
        g_h1T[0][j] = 0.f;
        g_h2T[0][j] = 0.f;
    }
}

// ---------------- generic 64x64 register-blocked fp32 GEMM tile (FFMA2) ----------------
// C[row0+64, col0+64] = act( A[., :K] * Weff[:K, .] + bias );  Weff per wtrans.
__device__ __forceinline__ void gemm64_body(
    const float* __restrict__ A, long lda,
    const float* __restrict__ A2, int ksplit, long lda2,
    const float* __restrict__ W, long ldw, int wtrans,
    const float* __restrict__ bias,
    float* __restrict__ C, long ldc,
    int K, int row0, int col0, int act,
    float* sA, float* sW)
{
    const int tid = threadIdx.x;
    const int tx = tid & 15;
    const int ty = tid >> 4;
    ull accp[4][2];
#pragma unroll
    for (int i = 0; i < 4; i++) { accp[i][0] = 0ull; accp[i][1] = 0ull; }

#pragma unroll 1
    for (int k0 = 0; k0 < K; k0 += 64) {
        const float* Ak = A; long ldak = lda; int kb = k0;
        if (A2 != nullptr && k0 >= ksplit) { Ak = A2; ldak = lda2; kb = k0 - ksplit; }

        __syncthreads();
#pragma unroll
        for (int p = 0; p < 4; p++) {
            int i = p * 256 + tid;
            int rr = i >> 4;
            int k4 = i & 15;
            float4 v = *(const float4*)(Ak + (long)(row0 + rr) * ldak + kb + k4 * 4);
            *(float4*)(sA + rr * 72 + k4 * 4) = v;
        }
        if (!wtrans) {
#pragma unroll
            for (int p = 0; p < 16; p++) {
                int i = p * 256 + tid;
                int kk = i >> 6, cc = i & 63;
                sW[kk * 72 + cc] = W[(long)(k0 + kk) * ldw + col0 + cc];
            }
        } else {
#pragma unroll
            for (int p = 0; p < 16; p++) {
                int i = p * 256 + tid;
                int kk = i & 63, cc = i >> 6;
                sW[kk * 72 + cc] = W[(long)(col0 + cc) * ldw + k0 + kk];
            }
        }
        __syncthreads();

#pragma unroll
        for (int k = 0; k < 64; k++) {
            ulonglong2 wv = *(const ulonglong2*)(sW + k * 72 + tx * 4);  // (w0,w1),(w2,w3)
#pragma unroll
            for (int i = 0; i < 4; i++) {
                float a = sA[(ty * 4 + i) * 72 + k];
                ull ap = pack2(a, a);
                accp[i][0] = fma2(ap, wv.x, accp[i][0]);
                accp[i][1] = fma2(ap, wv.y, accp[i][1]);
            }
        }
    }

#pragma unroll
    for (int i = 0; i < 4; i++) {
        float v0, v1, v2, v3;
        unpack2(v0, v1, accp[i][0]);
        unpack2(v2, v3, accp[i][1]);
        float vv[4] = {v0, v1, v2, v3};
#pragma unroll
        for (int j = 0; j < 4; j++) {
            int rr = row0 + ty * 4 + i;
            int cc = col0 + tx * 4 + j;
            float v = vv[j] + bias[cc];
            if (act) v = tanhf(v);
            C[(long)rr * ldc + cc] = v;
        }
    }
}

// ---------------- K1: precompute pre1[t] = x_t @ Wih_f[0,t] + b_f[0,t] ----------------
__global__ __launch_bounds__(256) void k_pre(
    const float* __restrict__ x, const float* __restrict__ Wih_f,
    const float* __restrict__ b_f)
{
    __shared__ float sA[64 * 72];
    __shared__ float sW[64 * 72];
    int t = blockIdx.y;
    int tile = blockIdx.x;
    int row0 = (tile >> 2) * 64;
    int col0 = (tile & 3) * 64;
    gemm64_body(x + (long)t * DD, (long)TT * DD,
                nullptr, 1 << 30, 0,
                Wih_f + (long)t * DD * HH, HH, 0,
                b_f + (long)t * HH,
                g_pre1 + (long)t * BB * HH, HH,
                DD, row0, col0, /*act=*/0, sA, sW);
}

// ================= K2: persistent sequential scan =================
// 16 independent row-groups (8 batch rows each) x 8 col-rank CTAs (32 cols each).
// All cross-CTA deps are within a row-group -> per-group 8-CTA atomic barrier.
// h stored column-major [col*BB+row]; smem tiles transposed hsT[k][r] so the
// inner dot uses ld.shared.v2.u64 + fma.rn.f32x2 (2 MACs/slot).

__device__ __forceinline__ void gbar(int grp, unsigned target) {
    __syncthreads();
    __threadfence();
    if (threadIdx.x == 0) {
        unsigned* ctr = &g_bar[grp * 32];
        atomicAdd(ctr, 1u);
        while (*(volatile unsigned*)ctr < target) __nanosleep(8);
        __threadfence();
    }
    __syncthreads();
}

// stage transposed tile: dst[k*8 + r] = srcT[k*BB + row_base + r], k = tid
__device__ __forceinline__ void stage_T(float* dst, const float* __restrict__ srcT,
                                        int row_base, int tid) {
    const float4* p = (const float4*)(srcT + (long)tid * BB + row_base);
    float4 v0 = __ldcg(p);
    float4 v1 = __ldcg(p + 1);
    *(float4*)(dst + tid * 8)     = v0;
    *(float4*)(dst + tid * 8 + 4) = v1;
}

// prefetch weight slice: w[j] = W[(32s+j)][col0+c] (coalesced across warp per j)
__device__ __forceinline__ void pf_w(float (&w)[32], const float* __restrict__ W,
                                     int s, int c, int col0) {
    const float* p = W + (long)(s * 32) * HH + col0 + c;
#pragma unroll
    for (int j = 0; j < 32; j++) w[j] = __ldg(p + (long)j * HH);
}

// packed dot over this thread's 32-k slice of an 8-row transposed tile
__device__ __forceinline__ void dotT(const float* hsT, const float (&w)[32], int s,
                                     ull& a01, ull& a23, ull& a45, ull& a67) {
#pragma unroll
    for (int k = 0; k < 32; k++) {
        const ulonglong2* p = (const ulonglong2*)(hsT + (s * 32 + k) * 8);
        ulonglong2 v0 = p[0];   // rows 0-1, 2-3 packed
        ulonglong2 v1 = p[1];   // rows 4-5, 6-7 packed
        ull wp = pack2(w[k], w[k]);
        a01 = fma2(v0.x, wp, a01);
        a23 = fma2(v0.y, wp, a23);
        a45 = fma2(v1.x, wp, a45);
        a67 = fma2(v1.y, wp, a67);
    }
}

// split-K reduction through smem; returns this thread's (row=s, col=c) value
__device__ __forceinline__ float reduceT(float* red, ull a01, ull a23, ull a45, ull a67,
                                         int s, int c) {
    float r[8];
    unpack2(r[0], r[1], a01);
    unpack2(r[2], r[3], a23);
    unpack2(r[4], r[5], a45);
    unpack2(r[6], r[7], a67);
#pragma unroll
    for (int q = 0; q < 8; q++) red[s * 256 + q * 32 + c] = r[q];
    __syncthreads();
    float v = 0.f;
#pragma unroll
    for (int q = 0; q < 8; q++) v += red[q * 256 + s * 32 + c];
    return v;
}

__global__ __launch_bounds__(256, 1)
void k_seq(const float* __restrict__ Wih_f, const float* __restrict__ Whh_f,
           const float* __restrict__ b_f)
{
    __shared__ float hsA[8 * HH];     // 8 KB  (transposed h tile 1)
    __shared__ float hsB[8 * HH];     // 8 KB  (transposed h tile 2)
    __shared__ float red[8 * 256];    // 8 KB
    const int tid = threadIdx.x;
    const int s = tid >> 5;
    const int c = tid & 31;
    const int grp = blockIdx.x >> 3;
    const int row_base = grp * 8;
    const int col0 = (blockIdx.x & 7) * 32;
    const int hT_off = (col0 + c) * BB + row_base + s;        // column-major slot
    const int rm_off = (row_base + s) * HH + col0 + c;        // row-major slot (pre1)

    const float* Whh1 = Whh_f;
    const float* Wih2 = Wih_f + (long)TT * DD * HH;
    const float* Whh2 = Whh_f + (long)TT * HH * HH;
    const float* b2   = b_f + (long)TT * HH;

    float wA[32], wB1[32], wB2[32];
    pf_w(wA, Whh1, s, c, col0);       // Whh1[t=0]
    unsigned bar = 0;

#pragma unroll 1
    for (int t = 0; t < TT; t++) {
        int pp = t & 1;
        int tn = (t < TT - 1) ? t + 1 : t;

        // ---- phase A: h1_new = tanh(pre1[t] + h1_prev @ Whh1[t]) ----
        stage_T(hsA, g_h1T[pp], row_base, tid);
        __syncthreads();                                   // also guards red[] reuse
        pf_w(wB1, Wih2 + (long)t * DD * HH, s, c, col0);   // prefetch for phase B
        pf_w(wB2, Whh2 + (long)t * HH * HH, s, c, col0);
        float pre = __ldg(g_pre1 + (long)t * BB * HH + rm_off);
        ull a01 = 0ull, a23 = 0ull, a45 = 0ull, a67 = 0ull;
        dotT(hsA, wA, s, a01, a23, a45, a67);
        float dA = reduceT(red, a01, a23, a45, a67, s, c);
        float h1v = tanhf(pre + dA);
        __stcg(g_h1T[pp ^ 1] + hT_off, h1v);
        gbar(grp, (++bar) * GSZ);

        // ---- phase B: h2_new = tanh(b2[t] + h1_new @ Wih2[t] + h2_prev @ Whh2[t]) ----
        stage_T(hsA, g_h1T[pp ^ 1], row_base, tid);
        stage_T(hsB, g_h2T[pp], row_base, tid);
        __syncthreads();
        pf_w(wA, Whh1 + (long)tn * HH * HH, s, c, col0);   // prefetch next step
        float acc2 = __ldg(b2 + (long)t * HH + col0 + c);
        a01 = 0ull; a23 = 0ull; a45 = 0ull; a67 = 0ull;
        dotT(hsA, wB1, s, a01, a23, a45, a67);
        dotT(hsB, wB2, s, a01, a23, a45, a67);
        float dB = reduceT(red, a01, a23, a45, a67, s, c);
        float h2v = tanhf(acc2 + dB);
        __stcg(g_h2T[pp ^ 1] + hT_off, h2v);
        gbar(grp, (++bar) * GSZ);
    }
}

// ---------------- transpose final forward h2 to row-major for the fc head ----------------
__global__ void k_tr() {
    int i = blockIdx.x * blockDim.x + threadIdx.x;   // 32768 threads
    int b = i >> 8, col = i & 255;
    g_h2rm[b * HH + col] = g_h2T[0][col * BB + b];   // T=256 even -> final in [0]
}

// ---------------- tail kernels: backward single step + fc head ----------------
__global__ __launch_bounds__(256) void k_tail_a(
    const float* __restrict__ x, const float* __restrict__ Wih_b,
    const float* __restrict__ b_b)
{
    __shared__ float sA[64 * 72];
    __shared__ float sW[64 * 72];
    int tile = blockIdx.x;
    int row0 = (tile >> 2) * 64, col0 = (tile & 3) * 64;
    gemm64_body(x + (long)(TT - 1) * DD, (long)TT * DD,
                nullptr, 1 << 30, 0,
                Wih_b + (long)(TT - 1) * DD * HH, HH, 0,
                b_b + (long)(TT - 1) * HH,
                g_h1bk, HH, DD, row0, col0, /*act=*/1, sA, sW);
}

__global__ __launch_bounds__(256) void k_tail_b(
    const float* __restrict__ Wih_b, const float* __restrict__ b_b)
{
    __shared__ float sA[64 * 72];
    __shared__ float sW[64 * 72];
    int tile = blockIdx.x;
    int row0 = (tile >> 2) * 64, col0 = (tile & 3) * 64;
    gemm64_body(g_h1bk, HH,
                nullptr, 1 << 30, 0,
                Wih_b + (long)(TT + TT - 1) * DD * HH, HH, 0,
                b_b + (long)(TT + TT - 1) * HH,
                g_h2bk, HH, HH, row0, col0, /*act=*/1, sA, sW);
}

__global__ __launch_bounds__(256) void k_tail_c(
    const float* __restrict__ fc_w, const float* __restrict__ fc_b,
    float* __restrict__ out)
{
    __shared__ float sA[64 * 72];
    __shared__ float sW[64 * 72];
    int tile = blockIdx.x;
    int row0 = (tile >> 2) * 64, col0 = (tile & 3) * 64;
    gemm64_body(g_h2rm, HH,
                g_h2bk, /*ksplit=*/HH, HH,
                fc_w, 2 * HH, /*wtrans=*/1,
                fc_b,
                out, HH, 2 * HH, row0, col0, /*act=*/0, sA, sW);
}

// ---------------- launcher ----------------
extern "C" void kernel_launch(void* const* d_in, const int* in_sizes, int n_in,
                              void* d_out, int out_size) {
    const float* x     = (const float*)d_in[0];
    const float* Wih_f = (const float*)d_in[1];
    const float* Whh_f = (const float*)d_in[2];
    const float* b_f   = (const float*)d_in[3];
    const float* Wih_b = (const float*)d_in[4];
    // d_in[5] = Whh_b: unused (backward output at t=T-1 starts from h0=0)
    const float* b_b   = (const float*)d_in[6];
    const float* fc_w  = (const float*)d_in[7];
    const float* fc_b  = (const float*)d_in[8];
    float* out = (float*)d_out;
    (void)in_sizes; (void)n_in; (void)out_size;

    k_reset<<<32, 256>>>();
    k_pre<<<dim3(8, TT), 256>>>(x, Wih_f, b_f);
    k_seq<<<NBLK, 256>>>(Wih_f, Whh_f, b_f);
    k_tr<<<128, 256>>>();
    k_tail_a<<<8, 256>>>(x, Wih_b, b_b);
    k_tail_b<<<8, 256>>>(Wih_b, b_b);
    k_tail_c<<<8, 256>>>(fc_w, fc_b, out);
}

// round 5
// speedup vs baseline: 1.2664x; 1.2664x over previous
#include <cuda_runtime.h>
#include <cuda_bf16.h>
#include <math.h>

// Problem constants
#define BB 128
#define TT 256
#define DD 256
#define HH 256

#define NBLK 128        // k_seq grid: 16 row-groups x 8 col-ranks
#define NGRP 16
#define GSZ  8          // CTAs per row-group (flag scope)

typedef unsigned long long ull;

// ---------------- packed f32x2 helpers (Blackwell FFMA2 via PTX) ----------------
__device__ __forceinline__ ull pack2(float lo, float hi) {
    ull r; asm("mov.b64 %0, {%1, %2};" : "=l"(r) : "f"(lo), "f"(hi)); return r;
}
__device__ __forceinline__ void unpack2(float& lo, float& hi, ull v) {
    asm("mov.b64 {%0, %1}, %2;" : "=f"(lo), "=f"(hi) : "l"(v));
}
__device__ __forceinline__ ull fma2(ull a, ull b, ull c) {
    ull d; asm("fma.rn.f32x2 %0, %1, %2, %3;" : "=l"(d) : "l"(a), "l"(b), "l"(c));
    return d;
}

// ---------------- device scratch ----------------
__device__ float g_pre1[TT * BB * HH];   // pre1[t][b][h] row-major
__device__ float g_h1T[2][HH * BB];      // hidden, column-major [col*BB+row]; h[t] in [t&1]
__device__ float g_h2T[2][HH * BB];
__device__ float g_h2rm[BB * HH];        // final forward h2, row-major (for fc)
__device__ float g_h1bk[BB * HH];
__device__ float g_h2bk[BB * HH];
__device__ unsigned g_f1[NGRP * 32];     // per-group monotonic flags (128B apart)
__device__ unsigned g_f2[NGRP * 32];

// ---------------- reset kernel (per-replay determinism) ----------------
__global__ void k_reset() {
    unsigned i = blockIdx.x * blockDim.x + threadIdx.x;
    if (i < NGRP * 32) { g_f1[i] = 0u; g_f2[i] = 0u; }
    for (unsigned j = i; j < BB * HH; j += gridDim.x * blockDim.x) {
        g_h2T[1][j] = 0.f;      // h2[-1] = 0 lives in buffer (-1)&1 = 1
    }
}

// ---------------- release/acquire flag ops ----------------
__device__ __forceinline__ void signal(unsigned* p) {
    __syncthreads();   // all threads' h stores precede the release (HB via bar.sync)
    if (threadIdx.x == 0)
        asm volatile("red.release.gpu.add.u32 [%0], 1;" :: "l"(p) : "memory");
}
__device__ __forceinline__ void waitflag(unsigned* p, unsigned target) {
    if (threadIdx.x == 0) {
        unsigned v;
        do {
            asm volatile("ld.acquire.gpu.u32 %0, [%1];" : "=r"(v) : "l"(p) : "memory");
        } while (v < target);
    }
    __syncthreads();
}

// ---------------- generic 64x64 register-blocked fp32 GEMM tile (FFMA2) ----------------
__device__ __forceinline__ void gemm64_body(
    const float* __restrict__ A, long lda,
    const float* __restrict__ A2, int ksplit, long lda2,
    const float* __restrict__ W, long ldw, int wtrans,
    const float* __restrict__ bias,
    float* __restrict__ C, long ldc,
    int K, int row0, int col0, int act,
    float* sA, float* sW)
{
    const int tid = threadIdx.x;
    const int tx = tid & 15;
    const int ty = tid >> 4;
    ull accp[4][2];
#pragma unroll
    for (int i = 0; i < 4; i++) { accp[i][0] = 0ull; accp[i][1] = 0ull; }

#pragma unroll 1
    for (int k0 = 0; k0 < K; k0 += 64) {
        const float* Ak = A; long ldak = lda; int kb = k0;
        if (A2 != nullptr && k0 >= ksplit) { Ak = A2; ldak = lda2; kb = k0 - ksplit; }

        __syncthreads();
#pragma unroll
        for (int p = 0; p < 4; p++) {
            int i = p * 256 + tid;
            int rr = i >> 4;
            int k4 = i & 15;
            float4 v = *(const float4*)(Ak + (long)(row0 + rr) * ldak + kb + k4 * 4);
            *(float4*)(sA + rr * 72 + k4 * 4) = v;
        }
        if (!wtrans) {
#pragma unroll
            for (int p = 0; p < 16; p++) {
                int i = p * 256 + tid;
                int kk = i >> 6, cc = i & 63;
                sW[kk * 72 + cc] = W[(long)(k0 + kk) * ldw + col0 + cc];
            }
        } else {
#pragma unroll
            for (int p = 0; p < 16; p++) {
                int i = p * 256 + tid;
                int kk = i & 63, cc = i >> 6;
                sW[kk * 72 + cc] = W[(long)(col0 + cc) * ldw + k0 + kk];
            }
        }
        __syncthreads();

#pragma unroll
        for (int k = 0; k < 64; k++) {
            ulonglong2 wv = *(const ulonglong2*)(sW + k * 72 + tx * 4);
#pragma unroll
            for (int i = 0; i < 4; i++) {
                float a = sA[(ty * 4 + i) * 72 + k];
                ull ap = pack2(a, a);
                accp[i][0] = fma2(ap, wv.x, accp[i][0]);
                accp[i][1] = fma2(ap, wv.y, accp[i][1]);
            }
        }
    }

#pragma unroll
    for (int i = 0; i < 4; i++) {
        float v0, v1, v2, v3;
        unpack2(v0, v1, accp[i][0]);
        unpack2(v2, v3, accp[i][1]);
        float vv[4] = {v0, v1, v2, v3};
#pragma unroll
        for (int j = 0; j < 4; j++) {
            int rr = row0 + ty * 4 + i;
            int cc = col0 + tx * 4 + j;
            float v = vv[j] + bias[cc];
            if (act) v = tanhf(v);
            C[(long)rr * ldc + cc] = v;
        }
    }
}

// ---------------- K1: precompute pre1[t] = x_t @ Wih_f[0,t] + b_f[0,t] ----------------
__global__ __launch_bounds__(256) void k_pre(
    const float* __restrict__ x, const float* __restrict__ Wih_f,
    const float* __restrict__ b_f)
{
    __shared__ float sA[64 * 72];
    __shared__ float sW[64 * 72];
    int t = blockIdx.y;
    int tile = blockIdx.x;
    int row0 = (tile >> 2) * 64;
    int col0 = (tile & 3) * 64;
    gemm64_body(x + (long)t * DD, (long)TT * DD,
                nullptr, 1 << 30, 0,
                Wih_f + (long)t * DD * HH, HH, 0,
                b_f + (long)t * HH,
                g_pre1 + (long)t * BB * HH, HH,
                DD, row0, col0, /*act=*/0, sA, sW);
}

// ================= K2: software-pipelined persistent sequential scan =================
// 16 independent row-groups (8 batch rows) x 8 col-rank CTAs (32 cols).
// Per step t:
//   1. dot1 = h1[t-1](smem) @ Whh1[t]; h1[t]=tanh(pre+.); store; signal f1  [no wait]
//      reload Whh1[t+1] in place (slack >1 phase)
//   2. wait f2>= t*8 (signaled last iter, hidden by dot1); stage h2[t-1]
//   3. dot2a = h2[t-1] @ Whh2[t]; prefetch pre1[t+1]; reload Whh2[t+1]
//   4. wait f1>=(t+1)*8 (hidden by dot2a); stage h1[t] (reused by next dot1)
//   5. dot2b = h1[t] @ Wih2[t]; h2[t]=tanh(b2+red); store; signal f2; reload Wih2[t+1]

// stage transposed tile: dst[k*8 + r] = srcT[k*BB + row_base + r], k = tid
__device__ __forceinline__ void stage_T(float* dst, const float* __restrict__ srcT,
                                        int row_base, int tid) {
    const float4* p = (const float4*)(srcT + (long)tid * BB + row_base);
    float4 v0 = __ldcg(p);
    float4 v1 = __ldcg(p + 1);
    *(float4*)(dst + tid * 8)     = v0;
    *(float4*)(dst + tid * 8 + 4) = v1;
}

// weight slice: w[j] = W[(32s+j)][col0+c] (coalesced across warp per j)
__device__ __forceinline__ void pf_w(float (&w)[32], const float* __restrict__ W,
                                     int s, int c, int col0) {
    const float* p = W + (long)(s * 32) * HH + col0 + c;
#pragma unroll
    for (int j = 0; j < 32; j++) w[j] = __ldg(p + (long)j * HH);
}

__device__ __forceinline__ void dotT(const float* hsT, const float (&w)[32], int s,
                                     ull& a01, ull& a23, ull& a45, ull& a67) {
#pragma unroll
    for (int k = 0; k < 32; k++) {
        const ulonglong2* p = (const ulonglong2*)(hsT + (s * 32 + k) * 8);
        ulonglong2 v0 = p[0];
        ulonglong2 v1 = p[1];
        ull wp = pack2(w[k], w[k]);
        a01 = fma2(v0.x, wp, a01);
        a23 = fma2(v0.y, wp, a23);
        a45 = fma2(v1.x, wp, a45);
        a67 = fma2(v1.y, wp, a67);
    }
}

__device__ __forceinline__ float reduceT(float* red, ull a01, ull a23, ull a45, ull a67,
                                         int s, int c) {
    float r[8];
    unpack2(r[0], r[1], a01);
    unpack2(r[2], r[3], a23);
    unpack2(r[4], r[5], a45);
    unpack2(r[6], r[7], a67);
#pragma unroll
    for (int q = 0; q < 8; q++) red[s * 256 + q * 32 + c] = r[q];
    __syncthreads();
    float v = 0.f;
#pragma unroll
    for (int q = 0; q < 8; q++) v += red[q * 256 + s * 32 + c];
    return v;
}

__global__ __launch_bounds__(256, 1)
void k_seq(const float* __restrict__ Wih_f, const float* __restrict__ Whh_f,
           const float* __restrict__ b_f)
{
    __shared__ float hsA[8 * HH];     // h1 tile (persists across iterations)
    __shared__ float hsB[8 * HH];     // h2 tile
    __shared__ float red[8 * 256];
    const int tid = threadIdx.x;
    const int s = tid >> 5;
    const int c = tid & 31;
    const int grp = blockIdx.x >> 3;
    const int row_base = grp * 8;
    const int col0 = (blockIdx.x & 7) * 32;
    const int hT_off = (col0 + c) * BB + row_base + s;
    const int rm_off = (row_base + s) * HH + col0 + c;

    const float* Whh1 = Whh_f;
    const float* Wih2 = Wih_f + (long)TT * DD * HH;
    const float* Whh2 = Whh_f + (long)TT * HH * HH;
    const float* b2   = b_f + (long)TT * HH;
    unsigned* f1 = &g_f1[grp * 32];
    unsigned* f2 = &g_f2[grp * 32];

    // prologue: h1[-1] = 0 in smem; initial weights; first pre
    for (int i = tid; i < 8 * HH; i += 256) hsA[i] = 0.f;
    float wH1[32], wI2[32], wH2[32];
    pf_w(wH1, Whh1, s, c, col0);
    pf_w(wH2, Whh2, s, c, col0);
    pf_w(wI2, Wih2, s, c, col0);
    float pre = __ldg(g_pre1 + rm_off);
    __syncthreads();

#pragma unroll 1
    for (int t = 0; t < TT; t++) {
        const int bufc = t & 1;
        const int bufp = bufc ^ 1;
        const int tn = (t < TT - 1) ? t + 1 : t;

        // ---- step 1: h1[t] = tanh(pre + h1[t-1] @ Whh1[t]) ----
        ull a01 = 0ull, a23 = 0ull, a45 = 0ull, a67 = 0ull;
        dotT(hsA, wH1, s, a01, a23, a45, a67);
        float dA = reduceT(red, a01, a23, a45, a67, s, c);
        float h1v = tanhf(pre + dA);
        __stcg(g_h1T[bufc] + hT_off, h1v);
        signal(f1);
        pf_w(wH1, Whh1 + (long)tn * HH * HH, s, c, col0);   // in-place reload, hidden

        // ---- step 2: wait h2[t-1]; stage it ----
        waitflag(f2, (unsigned)t * GSZ);
        stage_T(hsB, g_h2T[bufp], row_base, tid);
        __syncthreads();

        // ---- step 3: dot2a = h2[t-1] @ Whh2[t] ----
        a01 = 0ull; a23 = 0ull; a45 = 0ull; a67 = 0ull;
        dotT(hsB, wH2, s, a01, a23, a45, a67);
        pre = __ldg(g_pre1 + (long)tn * BB * HH + rm_off);  // prefetch next pre
        pf_w(wH2, Whh2 + (long)tn * HH * HH, s, c, col0);   // reload, hidden
        float bias = __ldg(b2 + (long)t * HH + col0 + c);

        // ---- step 4: wait h1[t]; stage it (also feeds next iteration's dot1) ----
        waitflag(f1, (unsigned)(t + 1) * GSZ);
        stage_T(hsA, g_h1T[bufc], row_base, tid);
        __syncthreads();

        // ---- step 5: dot2b = h1[t] @ Wih2[t]; h2[t] ----
        dotT(hsA, wI2, s, a01, a23, a45, a67);
        float dB = reduceT(red, a01, a23, a45, a67, s, c);
        float h2v = tanhf(bias + dB);
        __stcg(g_h2T[bufc] + hT_off, h2v);
        signal(f2);
        pf_w(wI2, Wih2 + (long)tn * DD * HH, s, c, col0);   // reload, hidden
    }
}

// ---------------- transpose final forward h2 to row-major for the fc head ----------------
__global__ void k_tr() {
    int i = blockIdx.x * blockDim.x + threadIdx.x;
    int b = i >> 8, col = i & 255;
    g_h2rm[b * HH + col] = g_h2T[1][col * BB + b];   // t=255 -> buffer 1
}

// ---------------- tail kernels: backward single step + fc head ----------------
__global__ __launch_bounds__(256) void k_tail_a(
    const float* __restrict__ x, const float* __restrict__ Wih_b,
    const float* __restrict__ b_b)
{
    __shared__ float sA[64 * 72];
    __shared__ float sW[64 * 72];
    int tile = blockIdx.x;
    int row0 = (tile >> 2) * 64, col0 = (tile & 3) * 64;
    gemm64_body(x + (long)(TT - 1) * DD, (long)TT * DD,
                nullptr, 1 << 30, 0,
                Wih_b + (long)(TT - 1) * DD * HH, HH, 0,
                b_b + (long)(TT - 1) * HH,
                g_h1bk, HH, DD, row0, col0, /*act=*/1, sA, sW);
}

__global__ __launch_bounds__(256) void k_tail_b(
    const float* __restrict__ Wih_b, const float* __restrict__ b_b)
{
    __shared__ float sA[64 * 72];
    __shared__ float sW[64 * 72];
    int tile = blockIdx.x;
    int row0 = (tile >> 2) * 64, col0 = (tile & 3) * 64;
    gemm64_body(g_h1bk, HH,
                nullptr, 1 << 30, 0,
                Wih_b + (long)(TT + TT - 1) * DD * HH, HH, 0,
                b_b + (long)(TT + TT - 1) * HH,
                g_h2bk, HH, HH, row0, col0, /*act=*/1, sA, sW);
}

__global__ __launch_bounds__(256) void k_tail_c(
    const float* __restrict__ fc_w, const float* __restrict__ fc_b,
    float* __restrict__ out)
{
    __shared__ float sA[64 * 72];
    __shared__ float sW[64 * 72];
    int tile = blockIdx.x;
    int row0 = (tile >> 2) * 64, col0 = (tile & 3) * 64;
    gemm64_body(g_h2rm, HH,
                g_h2bk, /*ksplit=*/HH, HH,
                fc_w, 2 * HH, /*wtrans=*/1,
                fc_b,
                out, HH, 2 * HH, row0, col0, /*act=*/0, sA, sW);
}

// ---------------- launcher ----------------
extern "C" void kernel_launch(void* const* d_in, const int* in_sizes, int n_in,
                              void* d_out, int out_size) {
    const float* x     = (const float*)d_in[0];
    const float* Wih_f = (const float*)d_in[1];
    const float* Whh_f = (const float*)d_in[2];
    const float* b_f   = (const float*)d_in[3];
    const float* Wih_b = (const float*)d_in[4];
    // d_in[5] = Whh_b: unused (backward output at t=T-1 starts from h0=0)
    const float* b_b   = (const float*)d_in[6];
    const float* fc_w  = (const float*)d_in[7];
    const float* fc_b  = (const float*)d_in[8];
    float* out = (float*)d_out;
    (void)in_sizes; (void)n_in; (void)out_size;

    k_reset<<<32, 256>>>();
    k_pre<<<dim3(8, TT), 256>>>(x, Wih_f, b_f);
    k_seq<<<NBLK, 256>>>(Wih_f, Whh_f, b_f);
    k_tr<<<128, 256>>>();
    k_tail_a<<<8, 256>>>(x, Wih_b, b_b);
    k_tail_b<<<8, 256>>>(Wih_b, b_b);
    k_tail_c<<<8, 256>>>(fc_w, fc_b, out);
}